// round 14
// baseline (speedup 1.0000x reference)
#include <cuda_runtime.h>
#include <math.h>

#define BB 4096
#define DD 2048
#define KK 8
#define PCOLS 25   // 3K+1

constexpr float RMIN = -5.0f;
constexpr float RMAX = 5.0f;
constexpr float MIN_BIN = 1e-3f;
constexpr float MIN_SLOPE = 1e-3f;
constexpr float MAX_SLOPE = 10.0f;

// Table 1: [8][DD] float4 {y_k, h, 1/w, c}  where c = -x_knot/w  (xi = fma(x, 1/w, c))
__device__ float4 g_main[8 * DD];
// Table 2: [8][DD] float2 {slope_j, slope_j+1}  (pair stored per bin)
__device__ float2 g_pair[8 * DD];
// Interior knots x_k[1..7], SoA [7][DD].
__device__ float  g_knots[7 * DD];

// Warp-per-d normalization: lane j holds param j (j<25).
__global__ void __launch_bounds__(256) norm_kernel(const float* __restrict__ params,
                                                   float* __restrict__ ld_out) {
    const int lane = threadIdx.x & 31;
    const int d = (blockIdx.x * blockDim.x + threadIdx.x) >> 5;

    const float* p = params + (size_t)d * PCOLS;
    const float raw = (lane < PCOLS) ? p[lane] : 0.f;
    const float sig = 1.f / (1.f + __expf(-raw));

    float gs = sig;
    gs += __shfl_xor_sync(0xffffffffu, gs, 4);
    gs += __shfl_xor_sync(0xffffffffu, gs, 2);
    gs += __shfl_xor_sync(0xffffffffu, gs, 1);

    const float rem = (RMAX - RMIN) - KK * MIN_BIN;
    const float val = MIN_BIN + sig * (rem / gs);
    const float slope = MIN_SLOPE + sig * (MAX_SLOPE - MIN_SLOPE);

    float scan = val;
    float t;
    t = __shfl_up_sync(0xffffffffu, scan, 1); if ((lane & 7) >= 1) scan += t;
    t = __shfl_up_sync(0xffffffffu, scan, 2); if ((lane & 7) >= 2) scan += t;
    t = __shfl_up_sync(0xffffffffu, scan, 4); if ((lane & 7) >= 4) scan += t;

    const int j = lane & 7;
    const float ht     = __shfl_sync(0xffffffffu, val,   8 + j);
    const float ht_inc = __shfl_sync(0xffffffffu, scan,  8 + j);
    const float sl_j   = __shfl_sync(0xffffffffu, slope, 16 + j);
    const float sl_j1  = __shfl_sync(0xffffffffu, slope, 17 + j);

    if (lane < 8) {
        const float rw = 1.f / val;
        const float lo = RMIN + scan - val;         // x_knot_j
        float4 v;
        v.x = RMIN + ht_inc - ht;                   // y_k
        v.y = ht;
        v.z = rw;
        v.w = -lo * rw;                             // c: xi = fma(x, rw, c)
        g_main[lane * DD + d] = v;
        g_pair[lane * DD + d] = make_float2(sl_j, sl_j1);
        if (lane < 7) g_knots[lane * DD + d] = RMIN + scan;
    }

    const int g = blockIdx.x * blockDim.x + threadIdx.x;
    if (g < BB) ld_out[g] = 0.f;
}

#define DT 256        // columns per CTA (== blockDim.x)
#define NCHUNK 512    // total row-chunks of 8 (BB/8)
#define GY 74         // persistent CTAs per column group: 8*74=592 = 4/SM, one wave

__global__ void __launch_bounds__(DT, 4) eval_kernel(const float* __restrict__ x,
                                                     float* __restrict__ y,
                                                     float* __restrict__ ld_out) {
    __shared__ float4 sm4[8 * DT];   // 32 KB
    __shared__ float2 smp[8 * DT];   // 16 KB  (48 KB total -> 4 CTAs/SM = 192 KB)

    const int tid = threadIdx.x;
    const int lane = tid & 31;
    const int d = blockIdx.x * DT + tid;

#pragma unroll
    for (int j = 0; j < 8; j++) {
        sm4[j * DT + tid] = g_main[j * DD + d];
        smp[j * DT + tid] = g_pair[j * DD + d];
    }

    const float v1 = g_knots[0 * DD + d];
    const float v2 = g_knots[1 * DD + d];
    const float v3 = g_knots[2 * DD + d];
    const float v4 = g_knots[3 * DD + d];
    const float v5 = g_knots[4 * DD + d];
    const float v6 = g_knots[5 * DD + d];
    const float v7 = g_knots[6 * DD + d];
    __syncthreads();

    // lane-dependent constants for the transpose reduction
    const bool k4 = (lane & 16) != 0;
    const bool k2 = (lane & 8)  != 0;
    const bool k1 = (lane & 4)  != 0;
    const int  red_row = ((lane >> 4) & 1) * 4 + ((lane >> 3) & 1) * 2 + ((lane >> 2) & 1);

    // persistent grid-stride over row-chunks: single wave
    for (int c = blockIdx.y; c < NCHUNK; c += GY) {
        const int b0 = c * 8;
        const float* xp = x + (size_t)b0 * DD + d;
        float*       yp = y + (size_t)b0 * DD + d;

        // front-batch the 8 global loads (MLP=8)
        float xin[8];
#pragma unroll
        for (int r = 0; r < 8; r++) xin[r] = __ldg(&xp[r * DD]);

        float dv[8];
#pragma unroll
        for (int r = 0; r < 8; r++) {
            const float xv = xin[r];
            // clamp: spline eval at xc is exact at both edges (deriv = s0 / sK)
            const float xc = fminf(fmaxf(xv, RMIN), RMAX);

            // 3-level binary search
            int bin = 0;
            if (xc >= v4) bin = 4;
            const float c2 = (bin & 4) ? v6 : v2;
            if (xc >= c2) bin += 2;
            const float c1 = (bin & 4) ? ((bin & 2) ? v7 : v5)
                                       : ((bin & 2) ? v3 : v1);
            if (xc >= c1) bin += 1;

            // conflict-free gathers: one LDS.128 + one LDS.64
            const int idx = bin * DT + tid;
            const float4 t  = sm4[idx];      // {y_k, h, rw, c}
            const float2 dk = smp[idx];      // {dk, dk1}

            // Horner form with shared subexpressions
            const float s   = t.y * t.z;              // h / w
            const float xi  = fmaf(xc, t.z, t.w);     // (xc - lo) / w
            const float sd  = s - dk.x;
            const float A   = (dk.y - s) - sd;

            const float ni  = fmaf(xi, sd, dk.x);
            const float t1  = fmaf(A, -xi, A);
            const float den = fmaf(xi, t1, s);
            const float rden = __fdividef(1.f, den);

            const float di  = fmaf(fmaf(A, xi, sd + sd), xi, dk.x);
            const float sr  = s * rden;
            dv[r] = di * sr * sr;                     // raw derivative; log deferred

            float yv = fmaf(t.y * xi * ni, rden, t.x);

            // linear tail extension: (x - xc) is 0 in-range
            const float tail = xv - xc;
            yv = fmaf(tail, (xv < 0.f) ? dk.x : dk.y, yv);

            yp[r * DD] = yv;
        }

        // Transpose-reduce: stages 1-3 MULTIPLY raw derivatives, ONE log per 16
        // elements, stages 4-5 ADD logs.
        float w4[4];
#pragma unroll
        for (int i = 0; i < 4; i++) {
            const float keep = k4 ? dv[i + 4] : dv[i];
            const float send = k4 ? dv[i] : dv[i + 4];
            w4[i] = keep * __shfl_xor_sync(0xffffffffu, send, 16);
        }
        float w2[2];
#pragma unroll
        for (int i = 0; i < 2; i++) {
            const float keep = k2 ? w4[i + 2] : w4[i];
            const float send = k2 ? w4[i] : w4[i + 2];
            w2[i] = keep * __shfl_xor_sync(0xffffffffu, send, 8);
        }
        const float pz = (k1 ? w2[1] : w2[0]) * __shfl_xor_sync(0xffffffffu, k1 ? w2[0] : w2[1], 4);

        float z = __logf(pz);           // one log per 16 elements
        z += __shfl_xor_sync(0xffffffffu, z, 2);
        z += __shfl_xor_sync(0xffffffffu, z, 1);

        if ((lane & 3) == 0) atomicAdd(&ld_out[b0 + red_row], z);
    }
}

extern "C" void kernel_launch(void* const* d_in, const int* in_sizes, int n_in,
                              void* d_out, int out_size) {
    const float* x;
    const float* params;
    if (in_sizes[0] == BB * DD) { x = (const float*)d_in[0]; params = (const float*)d_in[1]; }
    else                        { x = (const float*)d_in[1]; params = (const float*)d_in[0]; }

    float* y_out  = (float*)d_out;              // [B, D]
    float* ld_out = y_out + (size_t)BB * DD;    // [B]

    static bool configured = false;
    if (!configured) {
        cudaFuncSetAttribute(eval_kernel, cudaFuncAttributePreferredSharedMemoryCarveout, 100);
        configured = true;
    }

    norm_kernel<<<(DD * 32) / 256, 256>>>(params, ld_out);   // warp-per-d
    dim3 grid(DD / DT, GY);
    eval_kernel<<<grid, DT>>>(x, y_out, ld_out);
}

// round 15
// speedup vs baseline: 1.0102x; 1.0102x over previous
#include <cuda_runtime.h>
#include <math.h>

#define BB 4096
#define DD 2048
#define KK 8
#define PCOLS 25   // 3K+1

constexpr float RMIN = -5.0f;
constexpr float RMAX = 5.0f;
constexpr float MIN_BIN = 1e-3f;
constexpr float MIN_SLOPE = 1e-3f;
constexpr float MAX_SLOPE = 10.0f;

// Table 1: [8][DD] float4 {y_k, h, 1/w, c}  where c = -x_knot/w  (xi = fma(x, 1/w, c))
__device__ float4 g_main[8 * DD];
// Table 2: [8][DD] float2 {slope_j, slope_j+1}  (pair stored per bin)
__device__ float2 g_pair[8 * DD];
// Interior knots x_k[1..7], SoA [7][DD].
__device__ float  g_knots[7 * DD];

// Warp-per-d normalization: lane j holds param j (j<25).
__global__ void __launch_bounds__(256) norm_kernel(const float* __restrict__ params,
                                                   float* __restrict__ ld_out) {
    const int lane = threadIdx.x & 31;
    const int d = (blockIdx.x * blockDim.x + threadIdx.x) >> 5;

    const float* p = params + (size_t)d * PCOLS;
    const float raw = (lane < PCOLS) ? p[lane] : 0.f;
    const float sig = 1.f / (1.f + __expf(-raw));

    float gs = sig;
    gs += __shfl_xor_sync(0xffffffffu, gs, 4);
    gs += __shfl_xor_sync(0xffffffffu, gs, 2);
    gs += __shfl_xor_sync(0xffffffffu, gs, 1);

    const float rem = (RMAX - RMIN) - KK * MIN_BIN;
    const float val = MIN_BIN + sig * (rem / gs);
    const float slope = MIN_SLOPE + sig * (MAX_SLOPE - MIN_SLOPE);

    float scan = val;
    float t;
    t = __shfl_up_sync(0xffffffffu, scan, 1); if ((lane & 7) >= 1) scan += t;
    t = __shfl_up_sync(0xffffffffu, scan, 2); if ((lane & 7) >= 2) scan += t;
    t = __shfl_up_sync(0xffffffffu, scan, 4); if ((lane & 7) >= 4) scan += t;

    const int j = lane & 7;
    const float ht     = __shfl_sync(0xffffffffu, val,   8 + j);
    const float ht_inc = __shfl_sync(0xffffffffu, scan,  8 + j);
    const float sl_j   = __shfl_sync(0xffffffffu, slope, 16 + j);
    const float sl_j1  = __shfl_sync(0xffffffffu, slope, 17 + j);

    if (lane < 8) {
        const float rw = 1.f / val;
        const float lo = RMIN + scan - val;         // x_knot_j
        float4 v;
        v.x = RMIN + ht_inc - ht;                   // y_k
        v.y = ht;
        v.z = rw;
        v.w = -lo * rw;                             // c: xi = fma(x, rw, c)
        g_main[lane * DD + d] = v;
        g_pair[lane * DD + d] = make_float2(sl_j, sl_j1);
        if (lane < 7) g_knots[lane * DD + d] = RMIN + scan;
    }

    const int g = blockIdx.x * blockDim.x + threadIdx.x;
    if (g < BB) ld_out[g] = 0.f;
}

#define DT 256        // columns per CTA (== blockDim.x)
#define NCHUNK 512    // total row-chunks of 8 (BB/8)
#define GY 55         // persistent CTAs per column group: 8*55=440 <= 444 (3/SM), one wave

__global__ void __launch_bounds__(DT, 3) eval_kernel(const float* __restrict__ x,
                                                     float* __restrict__ y,
                                                     float* __restrict__ ld_out) {
    __shared__ float4 sm4[8 * DT];   // 32 KB
    __shared__ float2 smp[8 * DT];   // 16 KB  (48 KB total; 3 CTAs/SM = 144 KB)

    const int tid = threadIdx.x;
    const int lane = tid & 31;
    const int d = blockIdx.x * DT + tid;

#pragma unroll
    for (int j = 0; j < 8; j++) {
        sm4[j * DT + tid] = g_main[j * DD + d];
        smp[j * DT + tid] = g_pair[j * DD + d];
    }

    const float v1 = g_knots[0 * DD + d];
    const float v2 = g_knots[1 * DD + d];
    const float v3 = g_knots[2 * DD + d];
    const float v4 = g_knots[3 * DD + d];
    const float v5 = g_knots[4 * DD + d];
    const float v6 = g_knots[5 * DD + d];
    const float v7 = g_knots[6 * DD + d];
    __syncthreads();

    // lane-dependent constants for the transpose reduction
    const bool k4 = (lane & 16) != 0;
    const bool k2 = (lane & 8)  != 0;
    const bool k1 = (lane & 4)  != 0;
    const int  red_row = ((lane >> 4) & 1) * 4 + ((lane >> 3) & 1) * 2 + ((lane >> 2) & 1);

    // persistent grid-stride over row-chunks: single wave
    for (int c = blockIdx.y; c < NCHUNK; c += GY) {
        const int b0 = c * 8;
        const float* xp = x + (size_t)b0 * DD + d;
        float*       yp = y + (size_t)b0 * DD + d;

        // front-batch the 8 global loads (MLP=8)
        float xin[8];
#pragma unroll
        for (int r = 0; r < 8; r++) xin[r] = __ldg(&xp[r * DD]);

        float dv[8];
#pragma unroll
        for (int r = 0; r < 8; r++) {
            const float xv = xin[r];
            // clamp: spline eval at xc is exact at both edges (deriv = s0 / sK)
            const float xc = fminf(fmaxf(xv, RMIN), RMAX);

            // 3-level binary search
            int bin = 0;
            if (xc >= v4) bin = 4;
            const float c2 = (bin & 4) ? v6 : v2;
            if (xc >= c2) bin += 2;
            const float c1 = (bin & 4) ? ((bin & 2) ? v7 : v5)
                                       : ((bin & 2) ? v3 : v1);
            if (xc >= c1) bin += 1;

            // conflict-free gathers: one LDS.128 + one LDS.64
            const int idx = bin * DT + tid;
            const float4 t  = sm4[idx];      // {y_k, h, rw, c}
            const float2 dk = smp[idx];      // {dk, dk1}

            // Horner form with shared subexpressions
            const float s   = t.y * t.z;              // h / w
            const float xi  = fmaf(xc, t.z, t.w);     // (xc - lo) / w
            const float sd  = s - dk.x;
            const float A   = (dk.y - s) - sd;

            const float ni  = fmaf(xi, sd, dk.x);
            const float t1  = fmaf(A, -xi, A);
            const float den = fmaf(xi, t1, s);
            const float rden = __fdividef(1.f, den);

            const float di  = fmaf(fmaf(A, xi, sd + sd), xi, dk.x);
            const float sr  = s * rden;
            dv[r] = di * sr * sr;                     // raw derivative; log deferred

            float yv = fmaf(t.y * xi * ni, rden, t.x);

            // linear tail extension: (x - xc) is 0 in-range
            const float tail = xv - xc;
            yv = fmaf(tail, (xv < 0.f) ? dk.x : dk.y, yv);

            yp[r * DD] = yv;
        }

        // Transpose-reduce: stages 1-3 MULTIPLY raw derivatives, ONE log per 16
        // elements, stages 4-5 ADD logs.
        float w4[4];
#pragma unroll
        for (int i = 0; i < 4; i++) {
            const float keep = k4 ? dv[i + 4] : dv[i];
            const float send = k4 ? dv[i] : dv[i + 4];
            w4[i] = keep * __shfl_xor_sync(0xffffffffu, send, 16);
        }
        float w2[2];
#pragma unroll
        for (int i = 0; i < 2; i++) {
            const float keep = k2 ? w4[i + 2] : w4[i];
            const float send = k2 ? w4[i] : w4[i + 2];
            w2[i] = keep * __shfl_xor_sync(0xffffffffu, send, 8);
        }
        const float pz = (k1 ? w2[1] : w2[0]) * __shfl_xor_sync(0xffffffffu, k1 ? w2[0] : w2[1], 4);

        float z = __logf(pz);           // one log per 16 elements
        z += __shfl_xor_sync(0xffffffffu, z, 2);
        z += __shfl_xor_sync(0xffffffffu, z, 1);

        if ((lane & 3) == 0) atomicAdd(&ld_out[b0 + red_row], z);
    }
}

extern "C" void kernel_launch(void* const* d_in, const int* in_sizes, int n_in,
                              void* d_out, int out_size) {
    const float* x;
    const float* params;
    if (in_sizes[0] == BB * DD) { x = (const float*)d_in[0]; params = (const float*)d_in[1]; }
    else                        { x = (const float*)d_in[1]; params = (const float*)d_in[0]; }

    float* y_out  = (float*)d_out;              // [B, D]
    float* ld_out = y_out + (size_t)BB * DD;    // [B]

    static bool configured = false;
    if (!configured) {
        cudaFuncSetAttribute(eval_kernel, cudaFuncAttributePreferredSharedMemoryCarveout, 100);
        configured = true;
    }

    norm_kernel<<<(DD * 32) / 256, 256>>>(params, ld_out);   // warp-per-d
    dim3 grid(DD / DT, GY);
    eval_kernel<<<grid, DT>>>(x, y_out, ld_out);
}